// round 1
// baseline (speedup 1.0000x reference)
#include <cuda_runtime.h>
#include <math.h>

// Problem constants
#define NNODES 40000
#define NEDGES 640000
#define ETOT   (NEDGES + NNODES)   // edges + appended self loops
#define HDIM   128

// ---------------------------------------------------------------------------
// Scratch (device globals; no allocation allowed in kernel_launch)
// ---------------------------------------------------------------------------
__device__ float g_buf0[(size_t)NNODES * HDIM];   // 20.5 MB
__device__ float g_buf1[(size_t)NNODES * HDIM];   // 20.5 MB
__device__ float g_alpha[ETOT];
__device__ int   g_row[ETOT];
__device__ int   g_col[ETOT];
__device__ float g_deg[NNODES];
__device__ float g_dinv[NNODES];
__device__ float g_amax[NNODES];
__device__ float g_den[NNODES];
__device__ float g_acc[HDIM];
__device__ int   g_is64;

// ---------------------------------------------------------------------------
// Helpers
// ---------------------------------------------------------------------------
__device__ __forceinline__ void atomicMaxF(float* addr, float v) {
    // Correct for mixed-sign floats given init bits == 0x00000000 and the fact
    // that the true segment max is guaranteed >= 0 (self-loop alpha >= 0).
    if (v >= 0.0f) atomicMax((int*)addr, __float_as_int(v));
    else           atomicMin((unsigned int*)addr, __float_as_uint(v));
}

// ---------------------------------------------------------------------------
// Edge-index dtype detection + conversion
// edge_index is logically int64 [2, E] but may physically be int32 (JAX x64
// off). If int32, reading as int64 packs two consecutive indices: high word is
// almost surely nonzero somewhere in the first 1024 reads -> value >= NNODES.
// ---------------------------------------------------------------------------
__global__ void detect_dtype_kernel(const void* ei) {
    __shared__ int ok;
    if (threadIdx.x == 0) ok = 1;
    __syncthreads();
    const long long* p = (const long long*)ei;
    for (int i = threadIdx.x; i < 1024; i += blockDim.x) {
        long long v = p[i];
        if (v < 0 || v >= NNODES) atomicAnd(&ok, 0);
    }
    __syncthreads();
    if (threadIdx.x == 0) g_is64 = ok;
}

__global__ void convert_edges_kernel(const void* ei) {
    int e = blockIdx.x * blockDim.x + threadIdx.x;
    if (e >= ETOT) return;
    int r, c;
    if (e < NEDGES) {
        if (g_is64) {
            const long long* p = (const long long*)ei;
            r = (int)p[e];
            c = (int)p[NEDGES + e];
        } else {
            const int* p = (const int*)ei;
            r = p[e];
            c = p[NEDGES + e];
        }
    } else {
        r = c = e - NEDGES;   // appended self loop
    }
    g_row[e] = r;
    g_col[e] = c;
}

// ---------------------------------------------------------------------------
// Degrees (GCN norm). deg[n] = (#edges with row==n) + 1 (self loop).
// ---------------------------------------------------------------------------
__global__ void deg_init_kernel(float* deg) {
    int i = blockIdx.x * blockDim.x + threadIdx.x;
    if (i < NNODES) deg[i] = 1.0f;
}
__global__ void deg_acc_kernel(const int* __restrict__ row, float* deg) {
    int e = blockIdx.x * blockDim.x + threadIdx.x;
    if (e < NEDGES) atomicAdd(&deg[row[e]], 1.0f);
}
__global__ void dinv_kernel(const float* __restrict__ deg, float* dinv) {
    int i = blockIdx.x * blockDim.x + threadIdx.x;
    if (i < NNODES) dinv[i] = rsqrtf(deg[i]);
}

// ---------------------------------------------------------------------------
// SGEMM: C[M,128] = A[M,128] @ Weff[128,128] (+bias), where
// Weff = W (ADDW2=0) or W[0:128]+W[128:256] (ADDW2=1, folds the concat([h,h])).
// 128x128 tile per block, 256 threads, 8x8 register micro-tile.
// ---------------------------------------------------------------------------
template<bool ADDW2, bool BIAS>
__global__ __launch_bounds__(256) void sgemm_k128(
    const float* __restrict__ A, const float* __restrict__ W,
    const float* __restrict__ bias, float* __restrict__ C, int M)
{
    __shared__ float As[16][128];   // As[k][row]
    __shared__ float Ws[16][128];   // Ws[k][col]
    const int t  = threadIdx.x;
    const int tx = t & 15;          // col group
    const int ty = t >> 4;          // row group
    const int m0 = blockIdx.x * 128;

    float acc[8][8];
#pragma unroll
    for (int i = 0; i < 8; i++)
#pragma unroll
        for (int j = 0; j < 8; j++) acc[i][j] = 0.0f;

    for (int k0 = 0; k0 < 128; k0 += 16) {
        // A tile: 128 rows x 16 k, transposed into As[k][row]
#pragma unroll
        for (int it = 0; it < 2; it++) {
            int lin = t + it * 256;           // 0..511 float4 slots
            int row = lin >> 2;
            int k4  = (lin & 3) << 2;
            float4 v = make_float4(0.f, 0.f, 0.f, 0.f);
            if (m0 + row < M)
                v = *(const float4*)&A[(size_t)(m0 + row) * 128 + k0 + k4];
            As[k4 + 0][row] = v.x;
            As[k4 + 1][row] = v.y;
            As[k4 + 2][row] = v.z;
            As[k4 + 3][row] = v.w;
        }
        // W tile: 16 k x 128 cols (optionally folding the second half of W)
#pragma unroll
        for (int it = 0; it < 2; it++) {
            int lin = t + it * 256;
            int row = lin >> 5;               // 0..15
            int c4  = (lin & 31) << 2;        // 0..124
            float4 v = *(const float4*)&W[(size_t)(k0 + row) * 128 + c4];
            if (ADDW2) {
                float4 v2 = *(const float4*)&W[(size_t)(k0 + row + 128) * 128 + c4];
                v.x += v2.x; v.y += v2.y; v.z += v2.z; v.w += v2.w;
            }
            *(float4*)&Ws[row][c4] = v;
        }
        __syncthreads();

#pragma unroll
        for (int kk = 0; kk < 16; kk++) {
            float a[8], b[8];
            *(float4*)&a[0] = *(const float4*)&As[kk][ty * 8];
            *(float4*)&a[4] = *(const float4*)&As[kk][ty * 8 + 4];
            *(float4*)&b[0] = *(const float4*)&Ws[kk][tx * 8];
            *(float4*)&b[4] = *(const float4*)&Ws[kk][tx * 8 + 4];
#pragma unroll
            for (int i = 0; i < 8; i++)
#pragma unroll
                for (int j = 0; j < 8; j++)
                    acc[i][j] = fmaf(a[i], b[j], acc[i][j]);
        }
        __syncthreads();
    }

#pragma unroll
    for (int i = 0; i < 8; i++) {
        int r = m0 + ty * 8 + i;
        if (r < M) {
#pragma unroll
            for (int j4 = 0; j4 < 8; j4 += 4) {
                float4 v;
                v.x = acc[i][j4 + 0]; v.y = acc[i][j4 + 1];
                v.z = acc[i][j4 + 2]; v.w = acc[i][j4 + 3];
                if (BIAS) {
                    float4 bb = *(const float4*)&bias[tx * 8 + j4];
                    v.x += bb.x; v.y += bb.y; v.z += bb.z; v.w += bb.w;
                }
                *(float4*)&C[(size_t)r * 128 + tx * 8 + j4] = v;
            }
        }
    }
}

// ---------------------------------------------------------------------------
// GCN scatter: out[row] += xw[col] * dinv[row]*dinv[col], one warp per edge.
// ---------------------------------------------------------------------------
__global__ __launch_bounds__(256) void gcn_scatter_kernel(
    const int* __restrict__ rowA, const int* __restrict__ colA,
    const float* __restrict__ xw, const float* __restrict__ dinv,
    float* __restrict__ out)
{
    int w    = (blockIdx.x * 256 + threadIdx.x) >> 5;
    int lane = threadIdx.x & 31;
    if (w >= ETOT) return;
    int r = __ldg(&rowA[w]);
    int c = __ldg(&colA[w]);
    float nrm = __ldg(&dinv[r]) * __ldg(&dinv[c]);
    float4 v = *(const float4*)&xw[(size_t)c * 128 + lane * 4];
    float* o = &out[(size_t)r * 128 + lane * 4];
    atomicAdd(o + 0, v.x * nrm);
    atomicAdd(o + 1, v.y * nrm);
    atomicAdd(o + 2, v.z * nrm);
    atomicAdd(o + 3, v.w * nrm);
}

// h = relu(h + bias), in place
__global__ void gcn_finalize_kernel(float* __restrict__ h,
                                    const float* __restrict__ bias)
{
    int idx = blockIdx.x * blockDim.x + threadIdx.x;   // float4 index
    if (idx >= NNODES * 32) return;
    int f4 = (idx & 31) * 4;
    float4 v = *(float4*)&h[(size_t)idx * 4];
    float4 b = *(const float4*)&bias[f4];
    v.x = fmaxf(v.x + b.x, 0.0f);
    v.y = fmaxf(v.y + b.y, 0.0f);
    v.z = fmaxf(v.z + b.z, 0.0f);
    v.w = fmaxf(v.w + b.w, 0.0f);
    *(float4*)&h[(size_t)idx * 4] = v;
}

// ---------------------------------------------------------------------------
// GAT pass 1: alpha[e] = leakyrelu(dot(h[row], h[col]), 0.2) or -inf if the
// edge is an original self loop (masked). Also segment-max into amax.
// ---------------------------------------------------------------------------
__global__ __launch_bounds__(256) void gat_alpha_kernel(
    const int* __restrict__ rowA, const int* __restrict__ colA,
    const float* __restrict__ h, float* __restrict__ alpha,
    float* __restrict__ amax)
{
    int w    = (blockIdx.x * 256 + threadIdx.x) >> 5;
    int lane = threadIdx.x & 31;
    if (w >= ETOT) return;
    int r = __ldg(&rowA[w]);
    int c = __ldg(&colA[w]);
    bool valid = (w >= NEDGES) || (r != c);
    float4 a4 = *(const float4*)&h[(size_t)r * 128 + lane * 4];
    float4 b4 = *(const float4*)&h[(size_t)c * 128 + lane * 4];
    float d = a4.x * b4.x + a4.y * b4.y + a4.z * b4.z + a4.w * b4.w;
#pragma unroll
    for (int s = 16; s; s >>= 1) d += __shfl_xor_sync(0xffffffffu, d, s);
    if (lane == 0) {
        float al = valid ? fmaxf(d, 0.2f * d) : -INFINITY;  // leakyrelu(0.2)
        alpha[w] = al;
        if (valid) atomicMaxF(&amax[r], al);
    }
}

// GAT pass 2: a = exp(alpha - amax[row]) (exp(-inf)=0 handles mask), den += a
__global__ void gat_exp_kernel(const int* __restrict__ rowA,
                               float* __restrict__ alpha,
                               const float* __restrict__ amax,
                               float* __restrict__ den)
{
    int e = blockIdx.x * blockDim.x + threadIdx.x;
    if (e >= ETOT) return;
    int r = __ldg(&rowA[e]);
    float v = expf(alpha[e] - __ldg(&amax[r]));
    alpha[e] = v;
    if (v != 0.0f) atomicAdd(&den[r], v);
}

// GAT pass 3: out[row] += h[col] * a / max(den[row], 1e-16)
__global__ __launch_bounds__(256) void gat_scatter_kernel(
    const int* __restrict__ rowA, const int* __restrict__ colA,
    const float* __restrict__ h, const float* __restrict__ alpha,
    const float* __restrict__ den, float* __restrict__ out)
{
    int w    = (blockIdx.x * 256 + threadIdx.x) >> 5;
    int lane = threadIdx.x & 31;
    if (w >= ETOT) return;
    float a = __ldg(&alpha[w]);
    if (a == 0.0f) return;                      // masked or negligible
    int r = __ldg(&rowA[w]);
    int c = __ldg(&colA[w]);
    float wgt = a / fmaxf(__ldg(&den[r]), 1e-16f);
    float4 v = *(const float4*)&h[(size_t)c * 128 + lane * 4];
    float* o = &out[(size_t)r * 128 + lane * 4];
    atomicAdd(o + 0, v.x * wgt);
    atomicAdd(o + 1, v.y * wgt);
    atomicAdd(o + 2, v.z * wgt);
    atomicAdd(o + 3, v.w * wgt);
}

// ---------------------------------------------------------------------------
// Global mean pool: column sums -> acc[128]
// ---------------------------------------------------------------------------
__global__ void colsum_kernel(const float* __restrict__ h, float* __restrict__ acc)
{
    int col = threadIdx.x;                 // 128 threads
    int r0  = blockIdx.x * 256;
    int rend = r0 + 256;
    if (rend > NNODES) rend = NNODES;
    float s = 0.0f;
    for (int r = r0; r < rend; r++) s += h[(size_t)r * 128 + col];
    atomicAdd(&acc[col], s);
}

// out[0:128] = out[128:256] = acc / N   (mean of concat([h,h]))
__global__ void writeout_kernel(const float* __restrict__ acc, float* __restrict__ out)
{
    int i = threadIdx.x;                   // 256 threads
    out[i] = acc[i & 127] * (1.0f / (float)NNODES);
}

// ---------------------------------------------------------------------------
// Launch
// ---------------------------------------------------------------------------
extern "C" void kernel_launch(void* const* d_in, const int* in_sizes, int n_in,
                              void* d_out, int out_size)
{
    const float* x  = (const float*)d_in[0];
    const void*  ei = d_in[1];
    const float* Wg[3] = {(const float*)d_in[2], (const float*)d_in[6],  (const float*)d_in[10]};
    const float* bg[3] = {(const float*)d_in[3], (const float*)d_in[7],  (const float*)d_in[11]};
    const float* Wa[3] = {(const float*)d_in[4], (const float*)d_in[8],  (const float*)d_in[12]};
    const float* ba[3] = {(const float*)d_in[5], (const float*)d_in[9],  (const float*)d_in[13]};

    float *buf0, *buf1, *alpha, *deg, *dinv, *amax, *den, *acc;
    int *rowA, *colA;
    cudaGetSymbolAddress((void**)&buf0,  g_buf0);
    cudaGetSymbolAddress((void**)&buf1,  g_buf1);
    cudaGetSymbolAddress((void**)&alpha, g_alpha);
    cudaGetSymbolAddress((void**)&deg,   g_deg);
    cudaGetSymbolAddress((void**)&dinv,  g_dinv);
    cudaGetSymbolAddress((void**)&amax,  g_amax);
    cudaGetSymbolAddress((void**)&den,   g_den);
    cudaGetSymbolAddress((void**)&acc,   g_acc);
    cudaGetSymbolAddress((void**)&rowA,  g_row);
    cudaGetSymbolAddress((void**)&colA,  g_col);

    const int NB_N    = (NNODES + 255) / 256;
    const int NB_E    = (NEDGES + 255) / 256;
    const int NB_ET   = (ETOT + 255) / 256;
    const int NB_WARP = (ETOT + 7) / 8;          // warp-per-edge, 8 warps/block
    const int NB_GEMM = (NNODES + 127) / 128;    // 313
    const int NB_FIN  = (NNODES * 32 + 255) / 256;
    const int NB_COL  = (NNODES + 255) / 256;

    // Edge index dtype detection + conversion (appends self loops)
    detect_dtype_kernel<<<1, 256>>>(ei);
    convert_edges_kernel<<<NB_ET, 256>>>(ei);

    // Degrees / symmetric norm
    deg_init_kernel<<<NB_N, 256>>>(deg);
    deg_acc_kernel<<<NB_E, 256>>>(rowA, deg);
    dinv_kernel<<<NB_N, 256>>>(deg, dinv);

    for (int l = 0; l < 3; l++) {
        // --- GCN ---
        if (l == 0)
            sgemm_k128<false, false><<<NB_GEMM, 256>>>(x,    Wg[l], nullptr, buf1, NNODES);
        else
            sgemm_k128<true,  false><<<NB_GEMM, 256>>>(buf0, Wg[l], nullptr, buf1, NNODES);
        cudaMemsetAsync(buf0, 0, (size_t)NNODES * HDIM * sizeof(float), 0);
        gcn_scatter_kernel<<<NB_WARP, 256>>>(rowA, colA, buf1, dinv, buf0);
        gcn_finalize_kernel<<<NB_FIN, 256>>>(buf0, bg[l]);

        // --- GAT ---
        sgemm_k128<false, true><<<NB_GEMM, 256>>>(buf0, Wa[l], ba[l], buf1, NNODES);
        cudaMemsetAsync(amax, 0, NNODES * sizeof(float), 0);
        cudaMemsetAsync(den,  0, NNODES * sizeof(float), 0);
        gat_alpha_kernel<<<NB_WARP, 256>>>(rowA, colA, buf1, alpha, amax);
        gat_exp_kernel<<<NB_ET, 256>>>(rowA, alpha, amax, den);
        cudaMemsetAsync(buf0, 0, (size_t)NNODES * HDIM * sizeof(float), 0);
        gat_scatter_kernel<<<NB_WARP, 256>>>(rowA, colA, buf1, alpha, den, buf0);
        // buf0 now holds this layer's GAT output == next layer's input
    }

    // Global mean pool (concat halves are identical)
    cudaMemsetAsync(acc, 0, HDIM * sizeof(float), 0);
    colsum_kernel<<<NB_COL, 128>>>(buf0, acc);
    writeout_kernel<<<1, 256>>>(acc, (float*)d_out);
}

// round 2
// speedup vs baseline: 2.6935x; 2.6935x over previous
#include <cuda_runtime.h>
#include <math.h>

// Problem constants
#define NNODES 40000
#define NEDGES 640000
#define ETOT   (NEDGES + NNODES)   // edges + appended self loops
#define HDIM   128

// ---------------------------------------------------------------------------
// Scratch (device globals; no allocation allowed in kernel_launch)
// ---------------------------------------------------------------------------
__device__ float g_buf0[(size_t)NNODES * HDIM];   // 20.5 MB
__device__ float g_buf1[(size_t)NNODES * HDIM];   // 20.5 MB
__device__ int   g_row[ETOT];
__device__ int   g_col[ETOT];
__device__ int   g_csr[ETOT];            // packed: col | (invalid << 31)
__device__ int   g_cnt[NNODES];
__device__ int   g_offs[NNODES + 1];
__device__ int   g_cur[NNODES];
__device__ float g_dinv[NNODES];
__device__ float g_acc[HDIM];
__device__ int   g_is64;

// ---------------------------------------------------------------------------
// Edge-index dtype detection: edge_index is logically int64 [2,E] but may be
// int32 physically (JAX x64 off). Reading int32 data as int64 packs two
// indices -> almost surely produces a value outside [0, NNODES).
// ---------------------------------------------------------------------------
__global__ void detect_dtype_kernel(const void* ei) {
    __shared__ int ok;
    if (threadIdx.x == 0) ok = 1;
    __syncthreads();
    const long long* p = (const long long*)ei;
    for (int i = threadIdx.x; i < 1024; i += blockDim.x) {
        long long v = p[i];
        if (v < 0 || v >= NNODES) atomicAnd(&ok, 0);
    }
    __syncthreads();
    if (threadIdx.x == 0) g_is64 = ok;
}

__global__ void convert_edges_kernel(const void* ei) {
    int e = blockIdx.x * blockDim.x + threadIdx.x;
    if (e >= ETOT) return;
    int r, c;
    if (e < NEDGES) {
        if (g_is64) {
            const long long* p = (const long long*)ei;
            r = (int)p[e];
            c = (int)p[NEDGES + e];
        } else {
            const int* p = (const int*)ei;
            r = p[e];
            c = p[NEDGES + e];
        }
    } else {
        r = c = e - NEDGES;   // appended self loop
    }
    g_row[e] = r;
    g_col[e] = c;
}

// ---------------------------------------------------------------------------
// CSR build: count -> scan -> scatter
// ---------------------------------------------------------------------------
__global__ void cnt_init_kernel(int* cnt) {
    int i = blockIdx.x * blockDim.x + threadIdx.x;
    if (i < NNODES) cnt[i] = 1;     // appended self loop
}
__global__ void cnt_acc_kernel(const int* __restrict__ row, int* cnt) {
    int e = blockIdx.x * blockDim.x + threadIdx.x;
    if (e < NEDGES) atomicAdd(&cnt[row[e]], 1);
}

// Single-block exclusive scan over NNODES counts (chunked Hillis-Steele).
__global__ __launch_bounds__(1024) void scan_kernel(
    const int* __restrict__ cnt, int* __restrict__ offs,
    int* __restrict__ cur, float* __restrict__ dinv)
{
    __shared__ int totals[1024];
    const int CH = (NNODES + 1023) / 1024;   // 40
    int t = threadIdx.x;
    int base = t * CH;
    int s = 0;
    for (int i = 0; i < CH; i++) {
        int idx = base + i;
        if (idx < NNODES) s += cnt[idx];
    }
    totals[t] = s;
    __syncthreads();
    for (int off = 1; off < 1024; off <<= 1) {
        int v = (t >= off) ? totals[t - off] : 0;
        __syncthreads();
        if (t >= off) totals[t] += v;
        __syncthreads();
    }
    int run = (t == 0) ? 0 : totals[t - 1];
    for (int i = 0; i < CH; i++) {
        int idx = base + i;
        if (idx < NNODES) {
            offs[idx] = run;
            cur[idx]  = run;
            int c = cnt[idx];
            dinv[idx] = rsqrtf((float)c);   // GCN symmetric norm (deg >= 1)
            run += c;
        }
    }
    if (t == 0) offs[NNODES] = ETOT;
}

__global__ void csr_scatter_kernel(const int* __restrict__ row,
                                   const int* __restrict__ col,
                                   int* __restrict__ cur,
                                   int* __restrict__ csr)
{
    int e = blockIdx.x * blockDim.x + threadIdx.x;
    if (e >= ETOT) return;
    int r = row[e];
    int c = col[e];
    // original self-loops are masked out of GAT (bit 31), kept for GCN
    int invalid = (e < NEDGES && r == c) ? (int)0x80000000 : 0;
    int pos = atomicAdd(&cur[r], 1);
    csr[pos] = c | invalid;
}

// ---------------------------------------------------------------------------
// SGEMM: C[M,128] = A[M,128] @ Weff[128,128] (+bias).
// Weff = W, or W[0:128]+W[128:256] when ADDW2 (folds concat([h,h])).
// ---------------------------------------------------------------------------
template<bool ADDW2, bool BIAS>
__global__ __launch_bounds__(256) void sgemm_k128(
    const float* __restrict__ A, const float* __restrict__ W,
    const float* __restrict__ bias, float* __restrict__ C, int M)
{
    __shared__ float As[16][128];
    __shared__ float Ws[16][128];
    const int t  = threadIdx.x;
    const int tx = t & 15;
    const int ty = t >> 4;
    const int m0 = blockIdx.x * 128;

    float acc[8][8];
#pragma unroll
    for (int i = 0; i < 8; i++)
#pragma unroll
        for (int j = 0; j < 8; j++) acc[i][j] = 0.0f;

    for (int k0 = 0; k0 < 128; k0 += 16) {
#pragma unroll
        for (int it = 0; it < 2; it++) {
            int lin = t + it * 256;
            int row = lin >> 2;
            int k4  = (lin & 3) << 2;
            float4 v = make_float4(0.f, 0.f, 0.f, 0.f);
            if (m0 + row < M)
                v = *(const float4*)&A[(size_t)(m0 + row) * 128 + k0 + k4];
            As[k4 + 0][row] = v.x;
            As[k4 + 1][row] = v.y;
            As[k4 + 2][row] = v.z;
            As[k4 + 3][row] = v.w;
        }
#pragma unroll
        for (int it = 0; it < 2; it++) {
            int lin = t + it * 256;
            int row = lin >> 5;
            int c4  = (lin & 31) << 2;
            float4 v = *(const float4*)&W[(size_t)(k0 + row) * 128 + c4];
            if (ADDW2) {
                float4 v2 = *(const float4*)&W[(size_t)(k0 + row + 128) * 128 + c4];
                v.x += v2.x; v.y += v2.y; v.z += v2.z; v.w += v2.w;
            }
            *(float4*)&Ws[row][c4] = v;
        }
        __syncthreads();

#pragma unroll
        for (int kk = 0; kk < 16; kk++) {
            float a[8], b[8];
            *(float4*)&a[0] = *(const float4*)&As[kk][ty * 8];
            *(float4*)&a[4] = *(const float4*)&As[kk][ty * 8 + 4];
            *(float4*)&b[0] = *(const float4*)&Ws[kk][tx * 8];
            *(float4*)&b[4] = *(const float4*)&Ws[kk][tx * 8 + 4];
#pragma unroll
            for (int i = 0; i < 8; i++)
#pragma unroll
                for (int j = 0; j < 8; j++)
                    acc[i][j] = fmaf(a[i], b[j], acc[i][j]);
        }
        __syncthreads();
    }

#pragma unroll
    for (int i = 0; i < 8; i++) {
        int r = m0 + ty * 8 + i;
        if (r < M) {
#pragma unroll
            for (int j4 = 0; j4 < 8; j4 += 4) {
                float4 v;
                v.x = acc[i][j4 + 0]; v.y = acc[i][j4 + 1];
                v.z = acc[i][j4 + 2]; v.w = acc[i][j4 + 3];
                if (BIAS) {
                    float4 bb = *(const float4*)&bias[tx * 8 + j4];
                    v.x += bb.x; v.y += bb.y; v.z += bb.z; v.w += bb.w;
                }
                *(float4*)&C[(size_t)r * 128 + tx * 8 + j4] = v;
            }
        }
    }
}

// ---------------------------------------------------------------------------
// GCN gather (warp per destination node), fused bias + relu. No atomics.
// out[r] = relu( sum_{c in N(r)} dinv[r]*dinv[c]*xw[c] + bias )
// ---------------------------------------------------------------------------
__global__ __launch_bounds__(256) void gcn_gather_kernel(
    const float* __restrict__ xw, const int* __restrict__ offs,
    const int* __restrict__ csr, const float* __restrict__ dinv,
    const float* __restrict__ bias, float* __restrict__ out)
{
    int node = (blockIdx.x * 256 + threadIdx.x) >> 5;
    int lane = threadIdx.x & 31;
    if (node >= NNODES) return;
    int s = __ldg(&offs[node]);
    int e = __ldg(&offs[node + 1]);
    float dr = __ldg(&dinv[node]);
    float4 acc = make_float4(0.f, 0.f, 0.f, 0.f);
    for (int p = s; p < e; p++) {
        int c = __ldg(&csr[p]) & 0x7fffffff;
        float nrm = dr * __ldg(&dinv[c]);
        float4 v = *(const float4*)&xw[(size_t)c * 128 + lane * 4];
        acc.x = fmaf(v.x, nrm, acc.x);
        acc.y = fmaf(v.y, nrm, acc.y);
        acc.z = fmaf(v.z, nrm, acc.z);
        acc.w = fmaf(v.w, nrm, acc.w);
    }
    float4 b = *(const float4*)&bias[lane * 4];
    acc.x = fmaxf(acc.x + b.x, 0.0f);
    acc.y = fmaxf(acc.y + b.y, 0.0f);
    acc.z = fmaxf(acc.z + b.z, 0.0f);
    acc.w = fmaxf(acc.w + b.w, 0.0f);
    *(float4*)&out[(size_t)node * 128 + lane * 4] = acc;
}

// ---------------------------------------------------------------------------
// GAT gather (warp per destination node) with ONLINE softmax — single pass,
// one load of h[col] per edge, no atomics, no scratch.
// ---------------------------------------------------------------------------
__global__ __launch_bounds__(256) void gat_gather_kernel(
    const float* __restrict__ h, const int* __restrict__ offs,
    const int* __restrict__ csr, float* __restrict__ out)
{
    int node = (blockIdx.x * 256 + threadIdx.x) >> 5;
    int lane = threadIdx.x & 31;
    if (node >= NNODES) return;
    int s = __ldg(&offs[node]);
    int e = __ldg(&offs[node + 1]);

    float4 hr = *(const float4*)&h[(size_t)node * 128 + lane * 4];

    float m = -INFINITY;
    float den = 0.0f;
    float4 acc = make_float4(0.f, 0.f, 0.f, 0.f);

    for (int p = s; p < e; p++) {
        int raw = __ldg(&csr[p]);
        if (raw & 0x80000000) continue;            // masked original self loop
        int c = raw;
        float4 hc = *(const float4*)&h[(size_t)c * 128 + lane * 4];
        float d = hr.x * hc.x + hr.y * hc.y + hr.z * hc.z + hr.w * hc.w;
#pragma unroll
        for (int sh = 16; sh; sh >>= 1) d += __shfl_xor_sync(0xffffffffu, d, sh);
        float a = (d >= 0.0f) ? d : 0.2f * d;      // leaky_relu(0.2)
        if (a > m) {
            float sc = __expf(m - a);              // exp(-inf)=0 on first edge
            den *= sc;
            acc.x *= sc; acc.y *= sc; acc.z *= sc; acc.w *= sc;
            m = a;
        }
        float w = __expf(a - m);
        den += w;
        acc.x = fmaf(hc.x, w, acc.x);
        acc.y = fmaf(hc.y, w, acc.y);
        acc.z = fmaf(hc.z, w, acc.z);
        acc.w = fmaf(hc.w, w, acc.w);
    }
    float inv = 1.0f / fmaxf(den, 1e-16f);
    acc.x *= inv; acc.y *= inv; acc.z *= inv; acc.w *= inv;
    *(float4*)&out[(size_t)node * 128 + lane * 4] = acc;
}

// ---------------------------------------------------------------------------
// Global mean pool
// ---------------------------------------------------------------------------
__global__ void colsum_kernel(const float* __restrict__ h, float* __restrict__ acc)
{
    int col = threadIdx.x;                 // 128 threads
    int r0   = blockIdx.x * 256;
    int rend = r0 + 256;
    if (rend > NNODES) rend = NNODES;
    float s = 0.0f;
    for (int r = r0; r < rend; r++) s += h[(size_t)r * 128 + col];
    atomicAdd(&acc[col], s);
}

__global__ void writeout_kernel(const float* __restrict__ acc, float* __restrict__ out)
{
    int i = threadIdx.x;                   // 256 threads
    out[i] = acc[i & 127] * (1.0f / (float)NNODES);
}

// ---------------------------------------------------------------------------
// Launch
// ---------------------------------------------------------------------------
extern "C" void kernel_launch(void* const* d_in, const int* in_sizes, int n_in,
                              void* d_out, int out_size)
{
    const float* x  = (const float*)d_in[0];
    const void*  ei = d_in[1];
    const float* Wg[3] = {(const float*)d_in[2], (const float*)d_in[6],  (const float*)d_in[10]};
    const float* bg[3] = {(const float*)d_in[3], (const float*)d_in[7],  (const float*)d_in[11]};
    const float* Wa[3] = {(const float*)d_in[4], (const float*)d_in[8],  (const float*)d_in[12]};
    const float* ba[3] = {(const float*)d_in[5], (const float*)d_in[9],  (const float*)d_in[13]};

    float *buf0, *buf1, *dinv, *acc;
    int *rowA, *colA, *csr, *cnt, *offs, *cur;
    cudaGetSymbolAddress((void**)&buf0, g_buf0);
    cudaGetSymbolAddress((void**)&buf1, g_buf1);
    cudaGetSymbolAddress((void**)&dinv, g_dinv);
    cudaGetSymbolAddress((void**)&acc,  g_acc);
    cudaGetSymbolAddress((void**)&rowA, g_row);
    cudaGetSymbolAddress((void**)&colA, g_col);
    cudaGetSymbolAddress((void**)&csr,  g_csr);
    cudaGetSymbolAddress((void**)&cnt,  g_cnt);
    cudaGetSymbolAddress((void**)&offs, g_offs);
    cudaGetSymbolAddress((void**)&cur,  g_cur);

    const int NB_N    = (NNODES + 255) / 256;
    const int NB_E    = (NEDGES + 255) / 256;
    const int NB_ET   = (ETOT + 255) / 256;
    const int NB_WARP = (NNODES + 7) / 8;        // warp-per-node, 8 warps/block
    const int NB_GEMM = (NNODES + 127) / 128;
    const int NB_COL  = (NNODES + 255) / 256;

    // Edge conversion + CSR build
    detect_dtype_kernel<<<1, 256>>>(ei);
    convert_edges_kernel<<<NB_ET, 256>>>(ei);
    cnt_init_kernel<<<NB_N, 256>>>(cnt);
    cnt_acc_kernel<<<NB_E, 256>>>(rowA, cnt);
    scan_kernel<<<1, 1024>>>(cnt, offs, cur, dinv);
    csr_scatter_kernel<<<NB_ET, 256>>>(rowA, colA, cur, csr);

    for (int l = 0; l < 3; l++) {
        // --- GCN: GEMM -> gather(+bias+relu) ---
        if (l == 0)
            sgemm_k128<false, false><<<NB_GEMM, 256>>>(x,    Wg[l], nullptr, buf1, NNODES);
        else
            sgemm_k128<true,  false><<<NB_GEMM, 256>>>(buf0, Wg[l], nullptr, buf1, NNODES);
        gcn_gather_kernel<<<NB_WARP, 256>>>(buf1, offs, csr, dinv, bg[l], buf0);

        // --- GAT: GEMM(+bias) -> fused online-softmax gather ---
        sgemm_k128<false, true><<<NB_GEMM, 256>>>(buf0, Wa[l], ba[l], buf1, NNODES);
        gat_gather_kernel<<<NB_WARP, 256>>>(buf1, offs, csr, buf0);
    }

    // Global mean pool (concat halves identical)
    cudaMemsetAsync(acc, 0, HDIM * sizeof(float), 0);
    colsum_kernel<<<NB_COL, 128>>>(buf0, acc);
    writeout_kernel<<<1, 256>>>(acc, (float*)d_out);
}